// round 14
// baseline (speedup 1.0000x reference)
#include <cuda_runtime.h>
#include <cuda_fp16.h>
#include <cuda_bf16.h>

#define NN 100000
#define NE 1600000
#define HF 64
#define FULL 0xFFFFFFFFu
#define EW 64              // ELL width (P(deg>=64) ~ 1e-19)

// ---------------- scratch (device globals; no allocation allowed) ----------
__device__ __half g_h [NN * HF];   // h = x@W in fp16
__device__ float g_nf [NN * HF];
__device__ float g_nf2[NN * HF];
__device__ float g_el [NN];
__device__ float g_er [NN];
__device__ int   g_cur[NN];        // per-node edge count (ELL cursor)
__device__ int   g_ell[NN * EW];   // src ids grouped by dst, fixed stride

// ============================ ELL build =====================================
__global__ void ell_zero(int* __restrict__ cur) {
    int i = blockIdx.x * blockDim.x + threadIdx.x;
    if (i < NN) cur[i] = 0;
}

__global__ void ell_fill(const int* __restrict__ src, const int* __restrict__ dst,
                         int* __restrict__ cur, int* __restrict__ ell) {
    int e = blockIdx.x * blockDim.x + threadIdx.x;
    if (e >= NE) return;
    int d = dst[e];
    int p = atomicAdd(&cur[d], 1);
    ell[d * EW + p] = src[e];
}

// ==================== tensor-core GEMM (+ el/er), bf16 3-split ==============
// D = x@W: x=xh+xl, W=Wh+Wl (bf16 splits), D = xh*Wh + xh*Wl + xl*Wh.
// Software-pipelined: next chunk's global loads prefetched into registers
// before the mma loop so LDG latency hides behind tensor work.

#define KS 32
#define XP (KS + 4)

#define MMA_BF16(C, A0, A1, A2, A3, B0, B1)                              \
    asm volatile(                                                        \
        "mma.sync.aligned.m16n8k16.row.col.f32.bf16.bf16.f32 "           \
        "{%0,%1,%2,%3}, {%4,%5,%6,%7}, {%8,%9}, {%0,%1,%2,%3};\n"        \
        : "+f"(C[0]), "+f"(C[1]), "+f"(C[2]), "+f"(C[3])                 \
        : "r"(A0), "r"(A1), "r"(A2), "r"(A3), "r"(B0), "r"(B1))

__device__ __forceinline__ unsigned ldsm_u32(const __nv_bfloat16* p) {
    return *reinterpret_cast<const unsigned*>(p);
}

template <int K>
__global__ void __launch_bounds__(256)
gemm_el_er(const float* __restrict__ x, const float* __restrict__ W,
           const float* __restrict__ al, const float* __restrict__ ar,
           __half* __restrict__ h, float* __restrict__ el, float* __restrict__ er) {
    __shared__ __nv_bfloat16 sxh[128][XP];
    __shared__ __nv_bfloat16 sxl[128][XP];
    __shared__ __nv_bfloat16 swh[64][XP];
    __shared__ __nv_bfloat16 swl[64][XP];

    int tid = threadIdx.x;
    int warp = tid >> 5, lane = tid & 31;
    int g = lane >> 2, q = lane & 3;
    int base = blockIdx.x * 128;

    float c[8][4];
    #pragma unroll
    for (int nt = 0; nt < 8; nt++)
        #pragma unroll
        for (int i = 0; i < 4; i++) c[nt][i] = 0.0f;

    float4 px[4];   // prefetched x chunk (4 iters/thread)
    float4 pw[2];   // prefetched W chunk (2 iters/thread)

    // --- initial prefetch: chunk 0 ---
    #pragma unroll
    for (int it = 0; it < 4; it++) {
        int idx = tid + it * 256;
        int r = idx >> 3, qq = idx & 7;
        int row = base + r;
        px[it] = make_float4(0.f, 0.f, 0.f, 0.f);
        if (row < NN) px[it] = *(const float4*)&x[row * K + qq * 4];
    }
    #pragma unroll
    for (int it = 0; it < 2; it++) {
        int idx = tid + it * 256;
        int k = idx >> 4, qq = idx & 15;
        pw[it] = *(const float4*)&W[k * HF + qq * 4];
    }

    for (int kc = 0; kc < K; kc += KS) {
        // --- stage prefetched regs to smem (split hi/lo) ---
        #pragma unroll
        for (int it = 0; it < 4; it++) {
            int idx = tid + it * 256;
            int r = idx >> 3, qq = idx & 7;
            float4 v = px[it];
            __nv_bfloat162 hi01 = __floats2bfloat162_rn(v.x, v.y);
            __nv_bfloat162 hi23 = __floats2bfloat162_rn(v.z, v.w);
            __nv_bfloat162 lo01 = __floats2bfloat162_rn(
                v.x - __low2float(hi01), v.y - __high2float(hi01));
            __nv_bfloat162 lo23 = __floats2bfloat162_rn(
                v.z - __low2float(hi23), v.w - __high2float(hi23));
            *(__nv_bfloat162*)&sxh[r][qq * 4]     = hi01;
            *(__nv_bfloat162*)&sxh[r][qq * 4 + 2] = hi23;
            *(__nv_bfloat162*)&sxl[r][qq * 4]     = lo01;
            *(__nv_bfloat162*)&sxl[r][qq * 4 + 2] = lo23;
        }
        #pragma unroll
        for (int it = 0; it < 2; it++) {
            int idx = tid + it * 256;
            int k = idx >> 4, qq = idx & 15;
            float4 v = pw[it];
            float vv[4] = {v.x, v.y, v.z, v.w};
            #pragma unroll
            for (int e = 0; e < 4; e++) {
                __nv_bfloat16 hi = __float2bfloat16(vv[e]);
                __nv_bfloat16 lo = __float2bfloat16(vv[e] - __bfloat162float(hi));
                swh[qq * 4 + e][k] = hi;
                swl[qq * 4 + e][k] = lo;
            }
        }
        __syncthreads();

        // --- prefetch next chunk while tensor cores work ---
        if (kc + KS < K) {
            #pragma unroll
            for (int it = 0; it < 4; it++) {
                int idx = tid + it * 256;
                int r = idx >> 3, qq = idx & 7;
                int row = base + r;
                px[it] = make_float4(0.f, 0.f, 0.f, 0.f);
                if (row < NN)
                    px[it] = *(const float4*)&x[row * K + kc + KS + qq * 4];
            }
            #pragma unroll
            for (int it = 0; it < 2; it++) {
                int idx = tid + it * 256;
                int k = idx >> 4, qq = idx & 15;
                pw[it] = *(const float4*)&W[(kc + KS + k) * HF + qq * 4];
            }
        }

        #pragma unroll
        for (int ks = 0; ks < KS / 16; ks++) {
            int k16 = ks * 16;
            int r1 = warp * 16 + g;
            int ka = k16 + q * 2;
            unsigned ah0 = ldsm_u32(&sxh[r1][ka]);
            unsigned ah1 = ldsm_u32(&sxh[r1 + 8][ka]);
            unsigned ah2 = ldsm_u32(&sxh[r1][ka + 8]);
            unsigned ah3 = ldsm_u32(&sxh[r1 + 8][ka + 8]);
            unsigned alo0 = ldsm_u32(&sxl[r1][ka]);
            unsigned alo1 = ldsm_u32(&sxl[r1 + 8][ka]);
            unsigned alo2 = ldsm_u32(&sxl[r1][ka + 8]);
            unsigned alo3 = ldsm_u32(&sxl[r1 + 8][ka + 8]);
            #pragma unroll
            for (int nt = 0; nt < 8; nt++) {
                int n = nt * 8 + g;
                unsigned bh0 = ldsm_u32(&swh[n][ka]);
                unsigned bh1 = ldsm_u32(&swh[n][ka + 8]);
                unsigned bl0 = ldsm_u32(&swl[n][ka]);
                unsigned bl1 = ldsm_u32(&swl[n][ka + 8]);
                MMA_BF16(c[nt], ah0, ah1, ah2, ah3, bh0, bh1);
                MMA_BF16(c[nt], ah0, ah1, ah2, ah3, bl0, bl1);
                MMA_BF16(c[nt], alo0, alo1, alo2, alo3, bh0, bh1);
            }
        }
        if (kc + KS < K) __syncthreads();   // smem reuse guard
    }

    // epilogue: store h (fp16), fused el/er (fp32)
    int gr1 = base + warp * 16 + g;
    int gr2 = gr1 + 8;
    float pel1 = 0.f, per1 = 0.f, pel2 = 0.f, per2 = 0.f;
    #pragma unroll
    for (int nt = 0; nt < 8; nt++) {
        int col = nt * 8 + q * 2;
        float2 a2 = *(const float2*)&al[col];
        float2 r2 = *(const float2*)&ar[col];
        pel1 += c[nt][0] * a2.x + c[nt][1] * a2.y;
        per1 += c[nt][0] * r2.x + c[nt][1] * r2.y;
        pel2 += c[nt][2] * a2.x + c[nt][3] * a2.y;
        per2 += c[nt][2] * r2.x + c[nt][3] * r2.y;
        if (gr1 < NN) *(__half2*)&h[gr1 * HF + col] =
            __floats2half2_rn(c[nt][0], c[nt][1]);
        if (gr2 < NN) *(__half2*)&h[gr2 * HF + col] =
            __floats2half2_rn(c[nt][2], c[nt][3]);
    }
    #pragma unroll
    for (int o = 1; o <= 2; o <<= 1) {
        pel1 += __shfl_xor_sync(FULL, pel1, o);
        per1 += __shfl_xor_sync(FULL, per1, o);
        pel2 += __shfl_xor_sync(FULL, pel2, o);
        per2 += __shfl_xor_sync(FULL, per2, o);
    }
    if (q == 0) {
        if (gr1 < NN) { el[gr1] = pel1; er[gr1] = per1; }
        if (gr2 < NN) { el[gr2] = pel2; er[gr2] = per2; }
    }
}

// ============== fused per-node softmax + aggregate + bias + relu ============
// Warp per node; quarter-warp per edge row (8 lanes x 16B fp16 = 128B row).
// No max subtraction. node_base/node_count for split launches.
__global__ void __launch_bounds__(256)
gat_aggregate(const int* __restrict__ cur, const int* __restrict__ ell,
              const float* __restrict__ el, const float* __restrict__ er,
              const __half* __restrict__ h, const float* __restrict__ b,
              float* __restrict__ y, int node_base, int node_count) {
    int idx0 = (blockIdx.x * blockDim.x + threadIdx.x) >> 5;
    if (idx0 >= node_count) return;
    int node = node_base + idx0;
    int lane = threadIdx.x & 31;
    int qd   = lane >> 3;          // quarter 0..3
    int f8   = (lane & 7) * 8;     // features [f8, f8+8)

    int deg = cur[node];
    const int* row = &ell[node * EW];
    float erd = er[node];

    float sloc = 0.0f;
    float acc[8] = {0.f, 0.f, 0.f, 0.f, 0.f, 0.f, 0.f, 0.f};

    for (int base = 0; base < deg; base += 32) {
        int idx = base + lane;
        bool valid = idx < deg;
        int sn = valid ? row[idx] : 0;
        float w = 0.0f;
        if (valid) {
            float v = el[sn] + erd;
            v = v > 0.0f ? v : 0.2f * v;   // leaky relu
            w = __expf(v);
        }
        sloc += w;

        int cnt = deg - base; if (cnt > 32) cnt = 32;
        #pragma unroll 4
        for (int j = 0; j < cnt; j += 4) {
            int slot = j + qd;                      // <= 31 always
            int   se = __shfl_sync(FULL, sn, slot); // w=0 past cnt -> no-op
            float we = __shfl_sync(FULL, w,  slot);
            uint4 r = *(const uint4*)&h[se * HF + f8];
            float2 p0 = __half22float2(*(__half2*)&r.x);
            float2 p1 = __half22float2(*(__half2*)&r.y);
            float2 p2 = __half22float2(*(__half2*)&r.z);
            float2 p3 = __half22float2(*(__half2*)&r.w);
            acc[0] = fmaf(we, p0.x, acc[0]); acc[1] = fmaf(we, p0.y, acc[1]);
            acc[2] = fmaf(we, p1.x, acc[2]); acc[3] = fmaf(we, p1.y, acc[3]);
            acc[4] = fmaf(we, p2.x, acc[4]); acc[5] = fmaf(we, p2.y, acc[5]);
            acc[6] = fmaf(we, p3.x, acc[6]); acc[7] = fmaf(we, p3.y, acc[7]);
        }
    }

    // combine across quarters (xor 8 then 16 keeps same f8, merges edges)
    #pragma unroll
    for (int k = 0; k < 8; k++) {
        acc[k] += __shfl_xor_sync(FULL, acc[k], 8);
        acc[k] += __shfl_xor_sync(FULL, acc[k], 16);
    }
    float s = sloc;
    #pragma unroll
    for (int o = 16; o > 0; o >>= 1)
        s += __shfl_xor_sync(FULL, s, o);

    if (lane < 8) {
        float inv = (deg > 0) ? __fdividef(1.0f, s) : 0.0f;
        float4 ba = *(const float4*)&b[f8];
        float4 bb = *(const float4*)&b[f8 + 4];
        float4 oa, ob;
        oa.x = fmaxf(acc[0] * inv + ba.x, 0.f);
        oa.y = fmaxf(acc[1] * inv + ba.y, 0.f);
        oa.z = fmaxf(acc[2] * inv + ba.z, 0.f);
        oa.w = fmaxf(acc[3] * inv + ba.w, 0.f);
        ob.x = fmaxf(acc[4] * inv + bb.x, 0.f);
        ob.y = fmaxf(acc[5] * inv + bb.y, 0.f);
        ob.z = fmaxf(acc[6] * inv + bb.z, 0.f);
        ob.w = fmaxf(acc[7] * inv + bb.w, 0.f);
        *(float4*)&y[node * HF + f8]     = oa;
        *(float4*)&y[node * HF + f8 + 4] = ob;
    }
}

// ============================ host driver ===================================
#define NA 50000   // aggregate split point

static inline void launch_agg(const int* cur, const int* ell, const float* el,
                              const float* er, const __half* h, const float* b,
                              float* y) {
    gat_aggregate<<<(NA * 32 + 255) / 256, 256>>>(cur, ell, el, er, h, b, y, 0, NA);
    gat_aggregate<<<((NN - NA) * 32 + 255) / 256, 256>>>(cur, ell, el, er, h, b, y, NA, NN - NA);
}

extern "C" void kernel_launch(void* const* d_in, const int* in_sizes, int n_in,
                              void* d_out, int out_size) {
    const float* x   = (const float*)d_in[0];
    const int*   src = (const int*)  d_in[1];
    const int*   dst = (const int*)  d_in[2];
    const float* W1  = (const float*)d_in[3];
    const float* al1 = (const float*)d_in[4];
    const float* ar1 = (const float*)d_in[5];
    const float* b1  = (const float*)d_in[6];
    const float* W2  = (const float*)d_in[7];
    const float* al2 = (const float*)d_in[8];
    const float* ar2 = (const float*)d_in[9];
    const float* b2  = (const float*)d_in[10];
    const float* W3  = (const float*)d_in[11];
    const float* al3 = (const float*)d_in[12];
    const float* ar3 = (const float*)d_in[13];
    const float* b3  = (const float*)d_in[14];
    float* out = (float*)d_out;

    __half* h;
    float *nf, *nf2, *el, *er;
    int *cur, *ell;
    cudaGetSymbolAddress((void**)&h,   g_h);
    cudaGetSymbolAddress((void**)&nf,  g_nf);
    cudaGetSymbolAddress((void**)&nf2, g_nf2);
    cudaGetSymbolAddress((void**)&el,  g_el);
    cudaGetSymbolAddress((void**)&er,  g_er);
    cudaGetSymbolAddress((void**)&cur, g_cur);
    cudaGetSymbolAddress((void**)&ell, g_ell);

    static cudaStream_t s2 = nullptr;
    static cudaEvent_t evFork = nullptr, evJoin = nullptr;
    if (!s2) {
        cudaStreamCreateWithFlags(&s2, cudaStreamNonBlocking);
        cudaEventCreateWithFlags(&evFork, cudaEventDisableTiming);
        cudaEventCreateWithFlags(&evJoin, cudaEventDisableTiming);
    }

    // ---- fork: ELL build on s2, layer-1 GEMM on main stream ----
    cudaEventRecord(evFork, 0);
    cudaStreamWaitEvent(s2, evFork, 0);
    ell_zero<<<(NN + 255) / 256, 256, 0, s2>>>(cur);
    ell_fill<<<(NE + 255) / 256, 256, 0, s2>>>(src, dst, cur, ell);
    cudaEventRecord(evJoin, s2);

    gemm_el_er<128><<<(NN + 127) / 128, 256>>>(x, W1, al1, ar1, h, el, er);

    cudaStreamWaitEvent(0, evJoin, 0);

    launch_agg(cur, ell, el, er, h, b1, nf);

    gemm_el_er<64><<<(NN + 127) / 128, 256>>>(nf, W2, al2, ar2, h, el, er);
    launch_agg(cur, ell, el, er, h, b2, nf2);

    gemm_el_er<64><<<(NN + 127) / 128, 256>>>(nf2, W3, al3, ar3, h, el, er);
    launch_agg(cur, ell, el, er, h, b3, out);
}

// round 15
// speedup vs baseline: 1.0728x; 1.0728x over previous
#include <cuda_runtime.h>
#include <cuda_fp16.h>
#include <cuda_bf16.h>

#define NN 100000
#define NE 1600000
#define HF 64
#define FULL 0xFFFFFFFFu
#define EW 64              // ELL width (P(deg>=64) ~ 1e-19)

// ---------------- scratch (device globals; no allocation allowed) ----------
__device__ __half g_h [NN * HF];   // h = x@W in fp16
__device__ float g_nf [NN * HF];
__device__ float g_nf2[NN * HF];
__device__ float g_el [NN];
__device__ float g_er [NN];
__device__ int   g_cur[NN];        // per-node edge count (ELL cursor)
__device__ int   g_ell[NN * EW];   // src ids grouped by dst, fixed stride

// ============================ ELL build =====================================
__global__ void ell_zero(int* __restrict__ cur) {
    int i = blockIdx.x * blockDim.x + threadIdx.x;
    if (i < NN) cur[i] = 0;
}

__global__ void ell_fill(const int* __restrict__ src, const int* __restrict__ dst,
                         int* __restrict__ cur, int* __restrict__ ell) {
    int e = blockIdx.x * blockDim.x + threadIdx.x;
    if (e >= NE) return;
    int d = dst[e];
    int p = atomicAdd(&cur[d], 1);
    ell[d * EW + p] = src[e];
}

// ==================== tensor-core GEMM (+ el/er), bf16 3-split ==============
// D = x@W: x=xh+xl, W=Wh+Wl (bf16 splits), D = xh*Wh + xh*Wl + xl*Wh.
// Software-pipelined: next chunk's global loads prefetched into registers
// before the mma loop so LDG latency hides behind tensor work.

#define KS 32
#define XP (KS + 4)

#define MMA_BF16(C, A0, A1, A2, A3, B0, B1)                              \
    asm volatile(                                                        \
        "mma.sync.aligned.m16n8k16.row.col.f32.bf16.bf16.f32 "           \
        "{%0,%1,%2,%3}, {%4,%5,%6,%7}, {%8,%9}, {%0,%1,%2,%3};\n"        \
        : "+f"(C[0]), "+f"(C[1]), "+f"(C[2]), "+f"(C[3])                 \
        : "r"(A0), "r"(A1), "r"(A2), "r"(A3), "r"(B0), "r"(B1))

__device__ __forceinline__ unsigned ldsm_u32(const __nv_bfloat16* p) {
    return *reinterpret_cast<const unsigned*>(p);
}

template <int K>
__global__ void __launch_bounds__(256)
gemm_el_er(const float* __restrict__ x, const float* __restrict__ W,
           const float* __restrict__ al, const float* __restrict__ ar,
           __half* __restrict__ h, float* __restrict__ el, float* __restrict__ er) {
    __shared__ __nv_bfloat16 sxh[128][XP];
    __shared__ __nv_bfloat16 sxl[128][XP];
    __shared__ __nv_bfloat16 swh[64][XP];
    __shared__ __nv_bfloat16 swl[64][XP];

    int tid = threadIdx.x;
    int warp = tid >> 5, lane = tid & 31;
    int g = lane >> 2, q = lane & 3;
    int base = blockIdx.x * 128;

    float c[8][4];
    #pragma unroll
    for (int nt = 0; nt < 8; nt++)
        #pragma unroll
        for (int i = 0; i < 4; i++) c[nt][i] = 0.0f;

    float4 px[4];   // prefetched x chunk (4 iters/thread)
    float4 pw[2];   // prefetched W chunk (2 iters/thread)

    // --- initial prefetch: chunk 0 ---
    #pragma unroll
    for (int it = 0; it < 4; it++) {
        int idx = tid + it * 256;
        int r = idx >> 3, qq = idx & 7;
        int row = base + r;
        px[it] = make_float4(0.f, 0.f, 0.f, 0.f);
        if (row < NN) px[it] = *(const float4*)&x[row * K + qq * 4];
    }
    #pragma unroll
    for (int it = 0; it < 2; it++) {
        int idx = tid + it * 256;
        int k = idx >> 4, qq = idx & 15;
        pw[it] = *(const float4*)&W[k * HF + qq * 4];
    }

    for (int kc = 0; kc < K; kc += KS) {
        // --- stage prefetched regs to smem (split hi/lo) ---
        #pragma unroll
        for (int it = 0; it < 4; it++) {
            int idx = tid + it * 256;
            int r = idx >> 3, qq = idx & 7;
            float4 v = px[it];
            __nv_bfloat162 hi01 = __floats2bfloat162_rn(v.x, v.y);
            __nv_bfloat162 hi23 = __floats2bfloat162_rn(v.z, v.w);
            __nv_bfloat162 lo01 = __floats2bfloat162_rn(
                v.x - __low2float(hi01), v.y - __high2float(hi01));
            __nv_bfloat162 lo23 = __floats2bfloat162_rn(
                v.z - __low2float(hi23), v.w - __high2float(hi23));
            *(__nv_bfloat162*)&sxh[r][qq * 4]     = hi01;
            *(__nv_bfloat162*)&sxh[r][qq * 4 + 2] = hi23;
            *(__nv_bfloat162*)&sxl[r][qq * 4]     = lo01;
            *(__nv_bfloat162*)&sxl[r][qq * 4 + 2] = lo23;
        }
        #pragma unroll
        for (int it = 0; it < 2; it++) {
            int idx = tid + it * 256;
            int k = idx >> 4, qq = idx & 15;
            float4 v = pw[it];
            float vv[4] = {v.x, v.y, v.z, v.w};
            #pragma unroll
            for (int e = 0; e < 4; e++) {
                __nv_bfloat16 hi = __float2bfloat16(vv[e]);
                __nv_bfloat16 lo = __float2bfloat16(vv[e] - __bfloat162float(hi));
                swh[qq * 4 + e][k] = hi;
                swl[qq * 4 + e][k] = lo;
            }
        }
        __syncthreads();

        // --- prefetch next chunk while tensor cores work ---
        if (kc + KS < K) {
            #pragma unroll
            for (int it = 0; it < 4; it++) {
                int idx = tid + it * 256;
                int r = idx >> 3, qq = idx & 7;
                int row = base + r;
                px[it] = make_float4(0.f, 0.f, 0.f, 0.f);
                if (row < NN)
                    px[it] = *(const float4*)&x[row * K + kc + KS + qq * 4];
            }
            #pragma unroll
            for (int it = 0; it < 2; it++) {
                int idx = tid + it * 256;
                int k = idx >> 4, qq = idx & 15;
                pw[it] = *(const float4*)&W[(kc + KS + k) * HF + qq * 4];
            }
        }

        #pragma unroll
        for (int ks = 0; ks < KS / 16; ks++) {
            int k16 = ks * 16;
            int r1 = warp * 16 + g;
            int ka = k16 + q * 2;
            unsigned ah0 = ldsm_u32(&sxh[r1][ka]);
            unsigned ah1 = ldsm_u32(&sxh[r1 + 8][ka]);
            unsigned ah2 = ldsm_u32(&sxh[r1][ka + 8]);
            unsigned ah3 = ldsm_u32(&sxh[r1 + 8][ka + 8]);
            unsigned alo0 = ldsm_u32(&sxl[r1][ka]);
            unsigned alo1 = ldsm_u32(&sxl[r1 + 8][ka]);
            unsigned alo2 = ldsm_u32(&sxl[r1][ka + 8]);
            unsigned alo3 = ldsm_u32(&sxl[r1 + 8][ka + 8]);
            #pragma unroll
            for (int nt = 0; nt < 8; nt++) {
                int n = nt * 8 + g;
                unsigned bh0 = ldsm_u32(&swh[n][ka]);
                unsigned bh1 = ldsm_u32(&swh[n][ka + 8]);
                unsigned bl0 = ldsm_u32(&swl[n][ka]);
                unsigned bl1 = ldsm_u32(&swl[n][ka + 8]);
                MMA_BF16(c[nt], ah0, ah1, ah2, ah3, bh0, bh1);
                MMA_BF16(c[nt], ah0, ah1, ah2, ah3, bl0, bl1);
                MMA_BF16(c[nt], alo0, alo1, alo2, alo3, bh0, bh1);
            }
        }
        if (kc + KS < K) __syncthreads();   // smem reuse guard
    }

    // epilogue: store h (fp16), fused el/er (fp32)
    int gr1 = base + warp * 16 + g;
    int gr2 = gr1 + 8;
    float pel1 = 0.f, per1 = 0.f, pel2 = 0.f, per2 = 0.f;
    #pragma unroll
    for (int nt = 0; nt < 8; nt++) {
        int col = nt * 8 + q * 2;
        float2 a2 = *(const float2*)&al[col];
        float2 r2 = *(const float2*)&ar[col];
        pel1 += c[nt][0] * a2.x + c[nt][1] * a2.y;
        per1 += c[nt][0] * r2.x + c[nt][1] * r2.y;
        pel2 += c[nt][2] * a2.x + c[nt][3] * a2.y;
        per2 += c[nt][2] * r2.x + c[nt][3] * r2.y;
        if (gr1 < NN) *(__half2*)&h[gr1 * HF + col] =
            __floats2half2_rn(c[nt][0], c[nt][1]);
        if (gr2 < NN) *(__half2*)&h[gr2 * HF + col] =
            __floats2half2_rn(c[nt][2], c[nt][3]);
    }
    #pragma unroll
    for (int o = 1; o <= 2; o <<= 1) {
        pel1 += __shfl_xor_sync(FULL, pel1, o);
        per1 += __shfl_xor_sync(FULL, per1, o);
        pel2 += __shfl_xor_sync(FULL, pel2, o);
        per2 += __shfl_xor_sync(FULL, per2, o);
    }
    if (q == 0) {
        if (gr1 < NN) { el[gr1] = pel1; er[gr1] = per1; }
        if (gr2 < NN) { el[gr2] = pel2; er[gr2] = per2; }
    }
}

// ============== fused per-node softmax + aggregate + bias + relu ============
// Warp per node; quarter-warp per edge row (8 lanes x 16B fp16 = 128B row).
// No max subtraction. EXACT R13 version (unroll 2, regs 32, occ 83%).
__global__ void __launch_bounds__(256)
gat_aggregate(const int* __restrict__ cur, const int* __restrict__ ell,
              const float* __restrict__ el, const float* __restrict__ er,
              const __half* __restrict__ h, const float* __restrict__ b,
              float* __restrict__ y) {
    int node = (blockIdx.x * blockDim.x + threadIdx.x) >> 5;
    if (node >= NN) return;
    int lane = threadIdx.x & 31;
    int qd   = lane >> 3;          // quarter 0..3
    int f8   = (lane & 7) * 8;     // features [f8, f8+8)

    int deg = cur[node];
    const int* row = &ell[node * EW];
    float erd = er[node];

    float sloc = 0.0f;
    float acc[8] = {0.f, 0.f, 0.f, 0.f, 0.f, 0.f, 0.f, 0.f};

    for (int base = 0; base < deg; base += 32) {
        int idx = base + lane;
        bool valid = idx < deg;
        int sn = valid ? row[idx] : 0;
        float w = 0.0f;
        if (valid) {
            float v = el[sn] + erd;
            v = v > 0.0f ? v : 0.2f * v;   // leaky relu
            w = __expf(v);
        }
        sloc += w;

        int cnt = deg - base; if (cnt > 32) cnt = 32;
        #pragma unroll 2
        for (int j = 0; j < cnt; j += 4) {
            int slot = j + qd;                      // <= 31 always
            int   se = __shfl_sync(FULL, sn, slot); // w=0 past cnt -> no-op
            float we = __shfl_sync(FULL, w,  slot);
            uint4 r = *(const uint4*)&h[se * HF + f8];
            float2 p0 = __half22float2(*(__half2*)&r.x);
            float2 p1 = __half22float2(*(__half2*)&r.y);
            float2 p2 = __half22float2(*(__half2*)&r.z);
            float2 p3 = __half22float2(*(__half2*)&r.w);
            acc[0] = fmaf(we, p0.x, acc[0]); acc[1] = fmaf(we, p0.y, acc[1]);
            acc[2] = fmaf(we, p1.x, acc[2]); acc[3] = fmaf(we, p1.y, acc[3]);
            acc[4] = fmaf(we, p2.x, acc[4]); acc[5] = fmaf(we, p2.y, acc[5]);
            acc[6] = fmaf(we, p3.x, acc[6]); acc[7] = fmaf(we, p3.y, acc[7]);
        }
    }

    // combine across quarters (xor 8 then 16 keeps same f8, merges edges)
    #pragma unroll
    for (int k = 0; k < 8; k++) {
        acc[k] += __shfl_xor_sync(FULL, acc[k], 8);
        acc[k] += __shfl_xor_sync(FULL, acc[k], 16);
    }
    float s = sloc;
    #pragma unroll
    for (int o = 16; o > 0; o >>= 1)
        s += __shfl_xor_sync(FULL, s, o);

    if (lane < 8) {
        float inv = (deg > 0) ? __fdividef(1.0f, s) : 0.0f;
        float4 ba = *(const float4*)&b[f8];
        float4 bb = *(const float4*)&b[f8 + 4];
        float4 oa, ob;
        oa.x = fmaxf(acc[0] * inv + ba.x, 0.f);
        oa.y = fmaxf(acc[1] * inv + ba.y, 0.f);
        oa.z = fmaxf(acc[2] * inv + ba.z, 0.f);
        oa.w = fmaxf(acc[3] * inv + ba.w, 0.f);
        ob.x = fmaxf(acc[4] * inv + bb.x, 0.f);
        ob.y = fmaxf(acc[5] * inv + bb.y, 0.f);
        ob.z = fmaxf(acc[6] * inv + bb.z, 0.f);
        ob.w = fmaxf(acc[7] * inv + bb.w, 0.f);
        *(float4*)&y[node * HF + f8]     = oa;
        *(float4*)&y[node * HF + f8 + 4] = ob;
    }
}

// ============================ host driver ===================================
extern "C" void kernel_launch(void* const* d_in, const int* in_sizes, int n_in,
                              void* d_out, int out_size) {
    const float* x   = (const float*)d_in[0];
    const int*   src = (const int*)  d_in[1];
    const int*   dst = (const int*)  d_in[2];
    const float* W1  = (const float*)d_in[3];
    const float* al1 = (const float*)d_in[4];
    const float* ar1 = (const float*)d_in[5];
    const float* b1  = (const float*)d_in[6];
    const float* W2  = (const float*)d_in[7];
    const float* al2 = (const float*)d_in[8];
    const float* ar2 = (const float*)d_in[9];
    const float* b2  = (const float*)d_in[10];
    const float* W3  = (const float*)d_in[11];
    const float* al3 = (const float*)d_in[12];
    const float* ar3 = (const float*)d_in[13];
    const float* b3  = (const float*)d_in[14];
    float* out = (float*)d_out;

    __half* h;
    float *nf, *nf2, *el, *er;
    int *cur, *ell;
    cudaGetSymbolAddress((void**)&h,   g_h);
    cudaGetSymbolAddress((void**)&nf,  g_nf);
    cudaGetSymbolAddress((void**)&nf2, g_nf2);
    cudaGetSymbolAddress((void**)&el,  g_el);
    cudaGetSymbolAddress((void**)&er,  g_er);
    cudaGetSymbolAddress((void**)&cur, g_cur);
    cudaGetSymbolAddress((void**)&ell, g_ell);

    static cudaStream_t s2 = nullptr;
    static cudaEvent_t evFork = nullptr, evJoin = nullptr;
    if (!s2) {
        cudaStreamCreateWithFlags(&s2, cudaStreamNonBlocking);
        cudaEventCreateWithFlags(&evFork, cudaEventDisableTiming);
        cudaEventCreateWithFlags(&evJoin, cudaEventDisableTiming);
    }

    // ---- fork: ELL build on s2, layer-1 GEMM on main stream ----
    cudaEventRecord(evFork, 0);
    cudaStreamWaitEvent(s2, evFork, 0);
    ell_zero<<<(NN + 255) / 256, 256, 0, s2>>>(cur);
    ell_fill<<<(NE + 255) / 256, 256, 0, s2>>>(src, dst, cur, ell);
    cudaEventRecord(evJoin, s2);

    gemm_el_er<128><<<(NN + 127) / 128, 256>>>(x, W1, al1, ar1, h, el, er);

    cudaStreamWaitEvent(0, evJoin, 0);

    gat_aggregate<<<(NN * 32 + 255) / 256, 256>>>(cur, ell, el, er, h, b1, nf);

    gemm_el_er<64><<<(NN + 127) / 128, 256>>>(nf, W2, al2, ar2, h, el, er);
    gat_aggregate<<<(NN * 32 + 255) / 256, 256>>>(cur, ell, el, er, h, b2, nf2);

    gemm_el_er<64><<<(NN + 127) / 128, 256>>>(nf2, W3, al3, ar3, h, el, er);
    gat_aggregate<<<(NN * 32 + 255) / 256, 256>>>(cur, ell, el, er, h, b3, out);
}